// round 13
// baseline (speedup 1.0000x reference)
#include <cuda_runtime.h>
#include <math_constants.h>

#define B_     128
#define C_IN   512
#define HW     64
#define OUTD   256
#define EMB    4096
#define DDIM   4096
#define NSUB   32
#define NROWS  8192
#define NCLS   128
#define SPLIT  8
#define DSEG   (DDIM / SPLIT)   // 512
#define CSPL   4                // c-splits in argmin
#define CSEG   (C_IN / CSPL)    // 128

// ---- scratch (no allocations allowed) ----
__device__ float g_G[EMB * C_IN];     // G = cc @ W  [4096, 512] (present classes only)
__device__ float g_ce[EMB];           // ||cc_e||^2 - 2 b.cc_e
__device__ float g_Tsum[EMB];         // sum_d ts[e,d]
__device__ float g_T1[EMB];           // sum_d xlogy(ts, ts)
__device__ int   g_enc[NROWS];        // selected subclass row per pixel
__device__ int   g_present[NCLS];     // class presence flags
__device__ int   g_clist[NCLS];       // compact list of present classes
__device__ int   g_ncls;              // number of present classes
__device__ float g_pd[CSPL][NROWS * NSUB];   // argmin partial dots (4 MB)
__device__ float g_pssum[SPLIT][NROWS];
__device__ float g_pdot [SPLIT][NROWS];
__device__ float g_mpart[64];

typedef unsigned long long u64;
typedef unsigned int u32;

__device__ __forceinline__ u64 f2pack(float lo, float hi) {
    u64 r; asm("mov.b64 %0, {%1, %2};" : "=l"(r) : "f"(lo), "f"(hi)); return r;
}
__device__ __forceinline__ u64 ffma2(u64 a, u64 b, u64 c) {
    u64 d; asm("fma.rn.f32x2 %0, %1, %2, %3;" : "=l"(d) : "l"(a), "l"(b), "l"(c)); return d;
}
__device__ __forceinline__ float2 f2unpack(u64 v) {
    float2 f; asm("mov.b64 {%0, %1}, %2;" : "=f"(f.x), "=f"(f.y) : "l"(v)); return f;
}
__device__ __forceinline__ float to_tf32(float x) {
    float y; asm("cvt.rna.tf32.f32 %0, %1;" : "=f"(y) : "f"(x)); return y;
}
__device__ __forceinline__ void mma_tf32(float* d, const u32* a, u32 b0, u32 b1) {
    asm("mma.sync.aligned.m16n8k8.row.col.f32.tf32.tf32.f32 "
        "{%0,%1,%2,%3}, {%4,%5,%6,%7}, {%8,%9}, {%0,%1,%2,%3};"
        : "+f"(d[0]), "+f"(d[1]), "+f"(d[2]), "+f"(d[3])
        : "r"(a[0]), "r"(a[1]), "r"(a[2]), "r"(a[3]), "r"(b0), "r"(b1));
}

__inline__ __device__ float warp_sum(float v) {
#pragma unroll
    for (int o = 16; o; o >>= 1) v += __shfl_xor_sync(0xffffffffu, v, o);
    return v;
}

// ---------------------------------------------------------------- presence + compact list
__global__ void k_present(const int* __restrict__ labels) {
    int t = threadIdx.x;                 // 128
    if (t == 0) g_ncls = 0;
    if (t < NCLS) g_present[t] = 0;
    __syncthreads();
    if (t < B_) g_present[labels[t]] = 1;    // benign races, all write 1
    __syncthreads();
    if (t < NCLS && g_present[t]) {
        int s = atomicAdd(&g_ncls, 1);
        g_clist[s] = t;
    }
}

// ---------------------------------------------------------------- G = cc @ W via tf32 mma
// grid 512 (128 slots x 4 ctiles of 128 cols), block 128 (4 warps).
// Also computes g_ce from unrounded cc (ctile 0 writes).
__global__ void k_G(const float* __restrict__ cc, const float* __restrict__ W,
                    const float* __restrict__ bias) {
    int bx = blockIdx.x;
    int slot = bx >> 2, ctile = bx & 3;
    if (slot >= g_ncls) return;
    int cls = g_clist[slot];
    int e0 = cls * NSUB;
    int c0 = ctile * 128;

    __shared__ float As[32][260];   // [e][k], pad 4
    __shared__ float Bs[16][132];   // [k][c], pad 4
    int t = threadIdx.x;            // 128
    int lane = t & 31, w = t >> 5;

    // ---- stage A (32 x 256, tf32-rounded) + ce from exact values ----
    {
        int row = t >> 2;           // 0..31
        int cb  = (t & 3) * 64;
        const float* src = cc + (size_t)(e0 + row) * OUTD + cb;
        float ce = 0.f;
#pragma unroll
        for (int i = 0; i < 16; i++) {
            float4 v  = *(const float4*)(src + i * 4);
            float4 bv = *(const float4*)(bias + cb + i * 4);
            ce += v.x * (v.x - 2.f * bv.x) + v.y * (v.y - 2.f * bv.y)
                + v.z * (v.z - 2.f * bv.z) + v.w * (v.w - 2.f * bv.w);
            As[row][cb + i * 4 + 0] = to_tf32(v.x);
            As[row][cb + i * 4 + 1] = to_tf32(v.y);
            As[row][cb + i * 4 + 2] = to_tf32(v.z);
            As[row][cb + i * 4 + 3] = to_tf32(v.w);
        }
        ce += __shfl_xor_sync(0xffffffffu, ce, 1);
        ce += __shfl_xor_sync(0xffffffffu, ce, 2);
        if ((t & 3) == 0 && ctile == 0) g_ce[e0 + row] = ce;
    }

    float acc[2][4][4] = {};
    int r = lane >> 2, cq = lane & 3;
    int nb = w * 32;

    for (int kc = 0; kc < 16; kc++) {
        __syncthreads();            // As ready (kc=0) / Bs readers done (kc>0)
        {   // stage Bs: W[kc*16 .. +16)[c0 .. c0+128)
            int kk = t >> 3;        // 0..15
            int q  = (t & 7) * 16;  // 0..112
            const float* ws = W + (size_t)(kc * 16 + kk) * C_IN + c0 + q;
#pragma unroll
            for (int i = 0; i < 4; i++) {
                float4 v = *(const float4*)(ws + i * 4);
                Bs[kk][q + i * 4 + 0] = to_tf32(v.x);
                Bs[kk][q + i * 4 + 1] = to_tf32(v.y);
                Bs[kk][q + i * 4 + 2] = to_tf32(v.z);
                Bs[kk][q + i * 4 + 3] = to_tf32(v.w);
            }
        }
        __syncthreads();
#pragma unroll
        for (int kt2 = 0; kt2 < 2; kt2++) {
            int ka = kc * 16 + kt2 * 8;
            u32 a0[4], a1[4];
            a0[0] = __float_as_uint(As[r][ka + cq]);
            a0[1] = __float_as_uint(As[r + 8][ka + cq]);
            a0[2] = __float_as_uint(As[r][ka + cq + 4]);
            a0[3] = __float_as_uint(As[r + 8][ka + cq + 4]);
            a1[0] = __float_as_uint(As[16 + r][ka + cq]);
            a1[1] = __float_as_uint(As[24 + r][ka + cq]);
            a1[2] = __float_as_uint(As[16 + r][ka + cq + 4]);
            a1[3] = __float_as_uint(As[24 + r][ka + cq + 4]);
            int kb = kt2 * 8;
#pragma unroll
            for (int nt = 0; nt < 4; nt++) {
                u32 b0 = __float_as_uint(Bs[kb + cq][nb + nt * 8 + r]);
                u32 b1 = __float_as_uint(Bs[kb + cq + 4][nb + nt * 8 + r]);
                mma_tf32(acc[0][nt], a0, b0, b1);
                mma_tf32(acc[1][nt], a1, b0, b1);
            }
        }
    }
#pragma unroll
    for (int mt = 0; mt < 2; mt++)
#pragma unroll
    for (int nt = 0; nt < 4; nt++) {
        int row0 = e0 + mt * 16 + r;
        int col  = c0 + nb + nt * 8 + cq * 2;
        *(float2*)(g_G + (size_t)row0 * C_IN + col)       = make_float2(acc[mt][nt][0], acc[mt][nt][1]);
        *(float2*)(g_G + (size_t)(row0 + 8) * C_IN + col) = make_float2(acc[mt][nt][2], acc[mt][nt][3]);
    }
}

// ---------------------------------------------------------------- teacher row stats
__global__ void k_T(const float* __restrict__ ts) {
    int e = blockIdx.x;                 // 4096
    if (!g_present[e >> 5]) return;
    int t = threadIdx.x;                // 256
    const float4* row = (const float4*)(ts + (size_t)e * DDIM);
    float s = 0.f, t1 = 0.f;
    for (int i = t; i < DDIM / 4; i += 256) {
        float4 v = row[i];
        s += v.x + v.y + v.z + v.w;
        t1 += (v.x > 0.f ? v.x * __logf(v.x) : 0.f)
            + (v.y > 0.f ? v.y * __logf(v.y) : 0.f)
            + (v.z > 0.f ? v.z * __logf(v.z) : 0.f)
            + (v.w > 0.f ? v.w * __logf(v.w) : 0.f);
    }
    s = warp_sum(s); t1 = warp_sum(t1);
    __shared__ float s1[8], s2[8];
    if ((t & 31) == 0) { s1[t >> 5] = s; s2[t >> 5] = t1; }
    __syncthreads();
    if (t == 0) {
        float S = 0.f, T = 0.f;
#pragma unroll
        for (int i = 0; i < 8; i++) { S += s1[i]; T += s2[i]; }
        g_Tsum[e] = S; g_T1[e] = T;
    }
}

// ---------------------------------------------------------------- argmin partial dots
// grid = B_ * CSPL (512 blocks), block 256: hw = t&63, jg = t>>6.
// No x-staging: feat streamed directly (warp = contiguous 128B row), G staged once.
__global__ void __launch_bounds__(256, 8)
k_argmin_part(const float* __restrict__ feat, const int* __restrict__ labels) {
    int bx = blockIdx.x;
    int b  = bx >> 2;
    int cs = bx & 3;
    int cls = labels[b];
    __shared__ float GsT[CSEG][36];   // [c][j], row 144B (16B-aligned)
    int t  = threadIdx.x;             // 256
    int hw = t & 63, jg = t >> 6;     // jg 0..3 (8 subclasses each)

    // stage G slice [32 j][CSEG c] transposed -> GsT[c][j]; 1024 float4 loads
#pragma unroll
    for (int k = 0; k < 4; k++) {
        int i = t + 256 * k;
        int j = i >> 5, cq = i & 31;
        float4 v = *(const float4*)(g_G + (size_t)(cls * NSUB + j) * C_IN + cs * CSEG + cq * 4);
        GsT[cq * 4 + 0][j] = v.x; GsT[cq * 4 + 1][j] = v.y;
        GsT[cq * 4 + 2][j] = v.z; GsT[cq * 4 + 3][j] = v.w;
    }
    __syncthreads();

    u64 acc2[4] = {};
    const float* fb = feat + (size_t)b * C_IN * HW + cs * CSEG * HW + hw;

#pragma unroll 2
    for (int c0 = 0; c0 < CSEG; c0 += 8) {
        float x[8];
#pragma unroll
        for (int u = 0; u < 8; u++) x[u] = __ldcs(fb + (size_t)(c0 + u) * HW);
#pragma unroll
        for (int u = 0; u < 8; u++) {
            u64 xx = f2pack(x[u], x[u]);
            ulonglong2 gA = *(const ulonglong2*)&GsT[c0 + u][jg * 8];      // warp broadcast
            ulonglong2 gB = *(const ulonglong2*)&GsT[c0 + u][jg * 8 + 4];
            acc2[0] = ffma2(xx, gA.x, acc2[0]);
            acc2[1] = ffma2(xx, gA.y, acc2[1]);
            acc2[2] = ffma2(xx, gB.x, acc2[2]);
            acc2[3] = ffma2(xx, gB.y, acc2[3]);
        }
    }

    float* dst = g_pd[cs] + (size_t)(b * HW + hw) * NSUB + jg * 8;
    ulonglong2 v0; v0.x = acc2[0]; v0.y = acc2[1];
    ulonglong2 v1; v1.x = acc2[2]; v1.y = acc2[3];
    *(ulonglong2*)dst       = v0;
    *(ulonglong2*)(dst + 4) = v1;
}

// ---------------------------------------------------------------- argmin finalize
// grid = B_, block 64 (one thread per pixel)
__global__ void k_argmin_fin(const int* __restrict__ labels) {
    int b = blockIdx.x;
    int t = threadIdx.x;    // 64
    int cls = labels[b];
    float dsum[NSUB];
#pragma unroll
    for (int j = 0; j < NSUB; j++) dsum[j] = 0.f;
#pragma unroll
    for (int cs = 0; cs < CSPL; cs++) {
        const float4* p = (const float4*)(g_pd[cs] + (size_t)(b * HW + t) * NSUB);
#pragma unroll
        for (int q = 0; q < 8; q++) {
            float4 v = p[q];
            dsum[q * 4 + 0] += v.x; dsum[q * 4 + 1] += v.y;
            dsum[q * 4 + 2] += v.z; dsum[q * 4 + 3] += v.w;
        }
    }
    float bestv = CUDART_INF_F; int bestj = 0;
#pragma unroll
    for (int j = 0; j < NSUB; j++) {
        float v = g_ce[cls * NSUB + j] - 2.f * dsum[j];
        if (v < bestv) { bestv = v; bestj = j; }
    }
    g_enc[b * HW + t] = cls * NSUB + bestj;
}

// ---------------------------------------------------------------- fused KL partial pass
// grid = B_ * SPLIT; block 512 = 32 pixel-pairs x 16 d-lanes.
__global__ void __launch_bounds__(512, 4)
k_main(const float* __restrict__ scores, const float* __restrict__ ts,
       const int* __restrict__ labels) {
    int bx = blockIdx.x;
    int b  = bx >> 3;
    int sp = bx & 7;
    int cls = labels[b];
    int t = threadIdx.x;            // 512
    int hwg = t & 31, dl = t >> 5;  // pixels hwg*2, hwg*2+1 ; d-lane 0..15
    __shared__ float ts_s[NSUB][257];

    int e0 = g_enc[b * HW + hwg * 2];
    int e1 = g_enc[b * HW + hwg * 2 + 1];
    int j0 = e0 - cls * NSUB;
    int j1 = e1 - cls * NSUB;
    float dot0 = 0.f, dot1 = 0.f, ss0 = 0.f, ss1 = 0.f;
    const float* sb = scores + (size_t)b * DDIM * HW + hwg * 2;
    int dbase = sp * DSEG;

    for (int d0 = 0; d0 < DSEG; d0 += 256) {
        int dg = dbase + d0;
#pragma unroll
        for (int k = 0; k < 4; k++) {
            int i = t + 512 * k;
            int j = i >> 6, q = i & 63;
            float4 v = *(const float4*)(ts + (size_t)(cls * NSUB + j) * DDIM + dg + q * 4);
            ts_s[j][q * 4 + 0] = v.x; ts_s[j][q * 4 + 1] = v.y;
            ts_s[j][q * 4 + 2] = v.z; ts_s[j][q * 4 + 3] = v.w;
        }
        __syncthreads();
#pragma unroll 4
        for (int i = 0; i < 16; i++) {
            int dc = dl + 16 * i;                 // 0..255 within chunk
            float2 v = __ldcs((const float2*)(sb + (size_t)(dg + dc) * HW));
            float t0 = ts_s[j0][dc];
            float t1 = ts_s[j1][dc];
            dot0 = fmaf(t0, v.x, dot0); ss0 += __expf(v.x);
            dot1 = fmaf(t1, v.y, dot1); ss1 += __expf(v.y);
        }
        __syncthreads();
    }

    __shared__ float rs[16][66], rd[16][66];
    rs[dl][hwg * 2] = ss0; rs[dl][hwg * 2 + 1] = ss1;
    rd[dl][hwg * 2] = dot0; rd[dl][hwg * 2 + 1] = dot1;
    __syncthreads();
    if (t < 64) {
        float S = 0.f, D = 0.f;
#pragma unroll
        for (int l = 0; l < 16; l++) { S += rs[l][t]; D += rd[l][t]; }
        g_pssum[sp][b * HW + t] = S;
        g_pdot [sp][b * HW + t] = D;
    }
}

// ---------------------------------------------------------------- merge (64 blocks)
__global__ void k_merge(void) {
    int bx = blockIdx.x;        // 64
    int t  = threadIdx.x;       // 128
    int r  = bx * 128 + t;
    int e = g_enc[r];
    float ss = 0.f, dd = 0.f;
#pragma unroll
    for (int sp = 0; sp < SPLIT; sp++) { ss += g_pssum[sp][r]; dd += g_pdot[sp][r]; }
    float acc = g_T1[e] - dd + g_Tsum[e] * __logf(ss);
    acc = warp_sum(acc);
    __shared__ float sh[4];
    if ((t & 31) == 0) sh[t >> 5] = acc;
    __syncthreads();
    if (t == 0) g_mpart[bx] = sh[0] + sh[1] + sh[2] + sh[3];
}

// ---------------------------------------------------------------- final
__global__ void k_final(float* __restrict__ out) {
    int t = threadIdx.x;   // 64
    float v = g_mpart[t];
    v = warp_sum(v);
    __shared__ float sh[2];
    if ((t & 31) == 0) sh[t >> 5] = v;
    __syncthreads();
    if (t == 0) out[0] = (sh[0] + sh[1]) / (float)NROWS;
}

extern "C" void kernel_launch(void* const* d_in, const int* in_sizes, int n_in,
                              void* d_out, int out_size) {
    const float* feat   = (const float*)d_in[0];
    const float* scores = (const float*)d_in[1];
    const int*   labels = (const int*)  d_in[2];
    const float* W      = (const float*)d_in[3];
    const float* bias   = (const float*)d_in[4];
    const float* cc     = (const float*)d_in[5];
    const float* ts     = (const float*)d_in[6];
    float* out = (float*)d_out;

    k_present<<<1, 128>>>(labels);
    k_G<<<512, 128>>>(cc, W, bias);
    k_T<<<EMB, 256>>>(ts);
    k_argmin_part<<<B_ * CSPL, 256>>>(feat, labels);
    k_argmin_fin<<<B_, 64>>>(labels);
    k_main<<<B_ * SPLIT, 512>>>(scores, ts, labels);
    k_merge<<<64, 128>>>();
    k_final<<<1, 64>>>(out);
}

// round 15
// speedup vs baseline: 1.1550x; 1.1550x over previous
#include <cuda_runtime.h>
#include <math_constants.h>

#define B_     128
#define C_IN   512
#define HW     64
#define OUTD   256
#define EMB    4096
#define DDIM   4096
#define NSUB   32
#define NROWS  8192
#define NCLS   128
#define SPLIT  8
#define DSEG   (DDIM / SPLIT)   // 512
#define CSPL   8                // c-splits in argmin
#define CSEG   (C_IN / CSPL)    // 64
#define GBLK   512              // G-part blocks in fused setup kernel

// ---- scratch (no allocations allowed) ----
__device__ float g_G[EMB * C_IN];     // G = cc @ W  [4096, 512] (present classes only)
__device__ float g_ce[EMB];           // ||cc_e||^2 - 2 b.cc_e
__device__ float g_Tsum[EMB];         // sum_d ts[e,d]
__device__ float g_T1[EMB];           // sum_d xlogy(ts, ts)
__device__ int   g_enc[NROWS];        // selected subclass row per pixel
__device__ int   g_present[NCLS];     // class presence flags
__device__ int   g_clist[NCLS];       // compact list of present classes
__device__ int   g_ncls;              // number of present classes
__device__ float g_pd[CSPL][NROWS * NSUB];   // argmin partial dots (8 MB)
__device__ float g_pssum[SPLIT][NROWS];
__device__ float g_pdot [SPLIT][NROWS];
__device__ float g_mpart[64];

typedef unsigned long long u64;
typedef unsigned int u32;

__device__ __forceinline__ u64 f2pack(float lo, float hi) {
    u64 r; asm("mov.b64 %0, {%1, %2};" : "=l"(r) : "f"(lo), "f"(hi)); return r;
}
__device__ __forceinline__ u64 ffma2(u64 a, u64 b, u64 c) {
    u64 d; asm("fma.rn.f32x2 %0, %1, %2, %3;" : "=l"(d) : "l"(a), "l"(b), "l"(c)); return d;
}
__device__ __forceinline__ float2 f2unpack(u64 v) {
    float2 f; asm("mov.b64 {%0, %1}, %2;" : "=f"(f.x), "=f"(f.y) : "l"(v)); return f;
}
__device__ __forceinline__ float to_tf32(float x) {
    float y; asm("cvt.rna.tf32.f32 %0, %1;" : "=f"(y) : "f"(x)); return y;
}
__device__ __forceinline__ void mma_tf32(float* d, const u32* a, u32 b0, u32 b1) {
    asm("mma.sync.aligned.m16n8k8.row.col.f32.tf32.tf32.f32 "
        "{%0,%1,%2,%3}, {%4,%5,%6,%7}, {%8,%9}, {%0,%1,%2,%3};"
        : "+f"(d[0]), "+f"(d[1]), "+f"(d[2]), "+f"(d[3])
        : "r"(a[0]), "r"(a[1]), "r"(a[2]), "r"(a[3]), "r"(b0), "r"(b1));
}

__inline__ __device__ float warp_sum(float v) {
#pragma unroll
    for (int o = 16; o; o >>= 1) v += __shfl_xor_sync(0xffffffffu, v, o);
    return v;
}

// ---------------------------------------------------------------- presence + compact list
__global__ void k_present(const int* __restrict__ labels) {
    int t = threadIdx.x;                 // 128
    if (t == 0) g_ncls = 0;
    if (t < NCLS) g_present[t] = 0;
    __syncthreads();
    if (t < B_) g_present[labels[t]] = 1;    // benign races, all write 1
    __syncthreads();
    if (t < NCLS && g_present[t]) {
        int s = atomicAdd(&g_ncls, 1);
        g_clist[s] = t;
    }
}

// ---------------------------------------------------------------- fused setup (128 thr):
//   blocks [0, GBLK):     G = cc @ W via tf32 mma (32e x 128c tiles) + ce
//   blocks [GBLK, +EMB):  teacher stats (Tsum, T1)
__global__ void k_setup(const float* __restrict__ cc, const float* __restrict__ W,
                        const float* __restrict__ bias, const float* __restrict__ ts) {
    int bx = blockIdx.x;
    int t  = threadIdx.x;     // 128

    if (bx < GBLK) {
        // ---------------- G GEMM part (tf32 mma) ----------------
        int slot = bx >> 2, ctile = bx & 3;
        if (slot >= g_ncls) return;
        int cls = g_clist[slot];
        int e0 = cls * NSUB;
        int c0 = ctile * 128;

        __shared__ float As[32][260];   // [e][k], pad 4
        __shared__ float Bs[16][132];   // [k][c], pad 4
        int lane = t & 31, w = t >> 5;

        // stage A (32 x 256, tf32-rounded) + ce from exact values
        {
            int row = t >> 2;           // 0..31
            int cb  = (t & 3) * 64;
            const float* src = cc + (size_t)(e0 + row) * OUTD + cb;
            float ce = 0.f;
#pragma unroll
            for (int i = 0; i < 16; i++) {
                float4 v  = *(const float4*)(src + i * 4);
                float4 bv = *(const float4*)(bias + cb + i * 4);
                ce += v.x * (v.x - 2.f * bv.x) + v.y * (v.y - 2.f * bv.y)
                    + v.z * (v.z - 2.f * bv.z) + v.w * (v.w - 2.f * bv.w);
                As[row][cb + i * 4 + 0] = to_tf32(v.x);
                As[row][cb + i * 4 + 1] = to_tf32(v.y);
                As[row][cb + i * 4 + 2] = to_tf32(v.z);
                As[row][cb + i * 4 + 3] = to_tf32(v.w);
            }
            ce += __shfl_xor_sync(0xffffffffu, ce, 1);
            ce += __shfl_xor_sync(0xffffffffu, ce, 2);
            if ((t & 3) == 0 && ctile == 0) g_ce[e0 + row] = ce;
        }

        float acc[2][4][4] = {};
        int r = lane >> 2, cq = lane & 3;
        int nb = w * 32;

        for (int kc = 0; kc < 16; kc++) {
            __syncthreads();
            {   // stage Bs: W[kc*16 .. +16)[c0 .. c0+128)
                int kk = t >> 3;        // 0..15
                int q  = (t & 7) * 16;  // 0..112
                const float* ws = W + (size_t)(kc * 16 + kk) * C_IN + c0 + q;
#pragma unroll
                for (int i = 0; i < 4; i++) {
                    float4 v = *(const float4*)(ws + i * 4);
                    Bs[kk][q + i * 4 + 0] = to_tf32(v.x);
                    Bs[kk][q + i * 4 + 1] = to_tf32(v.y);
                    Bs[kk][q + i * 4 + 2] = to_tf32(v.z);
                    Bs[kk][q + i * 4 + 3] = to_tf32(v.w);
                }
            }
            __syncthreads();
#pragma unroll
            for (int kt2 = 0; kt2 < 2; kt2++) {
                int ka = kc * 16 + kt2 * 8;
                u32 a0[4], a1[4];
                a0[0] = __float_as_uint(As[r][ka + cq]);
                a0[1] = __float_as_uint(As[r + 8][ka + cq]);
                a0[2] = __float_as_uint(As[r][ka + cq + 4]);
                a0[3] = __float_as_uint(As[r + 8][ka + cq + 4]);
                a1[0] = __float_as_uint(As[16 + r][ka + cq]);
                a1[1] = __float_as_uint(As[24 + r][ka + cq]);
                a1[2] = __float_as_uint(As[16 + r][ka + cq + 4]);
                a1[3] = __float_as_uint(As[24 + r][ka + cq + 4]);
                int kb = kt2 * 8;
#pragma unroll
                for (int nt = 0; nt < 4; nt++) {
                    u32 b0 = __float_as_uint(Bs[kb + cq][nb + nt * 8 + r]);
                    u32 b1 = __float_as_uint(Bs[kb + cq + 4][nb + nt * 8 + r]);
                    mma_tf32(acc[0][nt], a0, b0, b1);
                    mma_tf32(acc[1][nt], a1, b0, b1);
                }
            }
        }
#pragma unroll
        for (int mt = 0; mt < 2; mt++)
#pragma unroll
        for (int nt = 0; nt < 4; nt++) {
            int row0 = e0 + mt * 16 + r;
            int col  = c0 + nb + nt * 8 + cq * 2;
            *(float2*)(g_G + (size_t)row0 * C_IN + col)       = make_float2(acc[mt][nt][0], acc[mt][nt][1]);
            *(float2*)(g_G + (size_t)(row0 + 8) * C_IN + col) = make_float2(acc[mt][nt][2], acc[mt][nt][3]);
        }
    } else {
        // ---------------- teacher stats part ----------------
        int e = bx - GBLK;
        if (!g_present[e >> 5]) return;
        const float4* row = (const float4*)(ts + (size_t)e * DDIM);
        float s = 0.f, t1 = 0.f;
#pragma unroll 2
        for (int i = t; i < DDIM / 4; i += 128) {
            float4 v = row[i];
            s += v.x + v.y + v.z + v.w;
            t1 += (v.x > 0.f ? v.x * __logf(v.x) : 0.f)
                + (v.y > 0.f ? v.y * __logf(v.y) : 0.f)
                + (v.z > 0.f ? v.z * __logf(v.z) : 0.f)
                + (v.w > 0.f ? v.w * __logf(v.w) : 0.f);
        }
        s = warp_sum(s); t1 = warp_sum(t1);
        __shared__ float s1[4], s2[4];
        if ((t & 31) == 0) { s1[t >> 5] = s; s2[t >> 5] = t1; }
        __syncthreads();
        if (t == 0) {
            g_Tsum[e] = s1[0] + s1[1] + s1[2] + s1[3];
            g_T1[e]   = s2[0] + s2[1] + s2[2] + s2[3];
        }
    }
}

// ---------------------------------------------------------------- argmin partial dots
// grid = B_ * CSPL (1024 blocks), block 256: hw = t&63, jg = t>>6 (4 groups x 8 subclasses).
// Staged: xs[64 c][64 hw] (16KB) + GsT[64 c][32 j] (9KB); single stage->sync->compute pass.
__global__ void __launch_bounds__(256, 8)
k_argmin_part(const float* __restrict__ feat, const int* __restrict__ labels) {
    int bx = blockIdx.x;
    int b  = bx >> 3;
    int cs = bx & 7;
    int cls = labels[b];
    __shared__ float xs[CSEG][64];    // [c][hw]
    __shared__ float GsT[CSEG][36];   // [c][j], row 144B
    int t  = threadIdx.x;             // 256
    int hw = t & 63, jg = t >> 6;     // jg 0..3

    const float* fb = feat + (size_t)b * C_IN * HW + cs * CSEG * HW;
    const float* gb = g_G + (size_t)cls * NSUB * C_IN + cs * CSEG;

    {   // stage xs: 1024 float4
        const float4* src = (const float4*)fb;
        float4* dst = (float4*)&xs[0][0];
#pragma unroll
        for (int k = 0; k < 4; k++) dst[t + 256 * k] = __ldcs(src + t + 256 * k);
    }
#pragma unroll
    for (int k = 0; k < 2; k++) {     // stage GsT: 512 float4 (32 j x 16 float4)
        int i = t + 256 * k;
        int j = i >> 4, q = i & 15;
        float4 v = *(const float4*)(gb + (size_t)j * C_IN + q * 4);
        GsT[q * 4 + 0][j] = v.x; GsT[q * 4 + 1][j] = v.y;
        GsT[q * 4 + 2][j] = v.z; GsT[q * 4 + 3][j] = v.w;
    }
    __syncthreads();

    u64 acc2[4] = {};
#pragma unroll
    for (int c = 0; c < CSEG; c++) {
        u64 xx = f2pack(xs[c][hw], xs[c][hw]);
        ulonglong2 gA = *(const ulonglong2*)&GsT[c][jg * 8];      // warp-uniform broadcast
        ulonglong2 gB = *(const ulonglong2*)&GsT[c][jg * 8 + 4];
        acc2[0] = ffma2(xx, gA.x, acc2[0]);
        acc2[1] = ffma2(xx, gA.y, acc2[1]);
        acc2[2] = ffma2(xx, gB.x, acc2[2]);
        acc2[3] = ffma2(xx, gB.y, acc2[3]);
    }

    float* dst = g_pd[cs] + (size_t)(b * HW + hw) * NSUB + jg * 8;
    ulonglong2 v0; v0.x = acc2[0]; v0.y = acc2[1];
    ulonglong2 v1; v1.x = acc2[2]; v1.y = acc2[3];
    *(ulonglong2*)dst       = v0;
    *(ulonglong2*)(dst + 4) = v1;
}

// ---------------------------------------------------------------- argmin finalize
// grid = B_, block 64 (one thread per pixel)
__global__ void k_argmin_fin(const int* __restrict__ labels) {
    int b = blockIdx.x;
    int t = threadIdx.x;    // 64
    int cls = labels[b];
    float dsum[NSUB];
#pragma unroll
    for (int j = 0; j < NSUB; j++) dsum[j] = 0.f;
#pragma unroll
    for (int cs = 0; cs < CSPL; cs++) {
        const float4* p = (const float4*)(g_pd[cs] + (size_t)(b * HW + t) * NSUB);
#pragma unroll
        for (int q = 0; q < 8; q++) {
            float4 v = p[q];
            dsum[q * 4 + 0] += v.x; dsum[q * 4 + 1] += v.y;
            dsum[q * 4 + 2] += v.z; dsum[q * 4 + 3] += v.w;
        }
    }
    float bestv = CUDART_INF_F; int bestj = 0;
#pragma unroll
    for (int j = 0; j < NSUB; j++) {
        float v = g_ce[cls * NSUB + j] - 2.f * dsum[j];
        if (v < bestv) { bestv = v; bestj = j; }
    }
    g_enc[b * HW + t] = cls * NSUB + bestj;
}

// ---------------------------------------------------------------- fused KL partial pass
// grid = B_ * SPLIT; block 512 = 32 pixel-pairs x 16 d-lanes.
__global__ void __launch_bounds__(512, 4)
k_main(const float* __restrict__ scores, const float* __restrict__ ts,
       const int* __restrict__ labels) {
    int bx = blockIdx.x;
    int b  = bx >> 3;
    int sp = bx & 7;
    int cls = labels[b];
    int t = threadIdx.x;            // 512
    int hwg = t & 31, dl = t >> 5;  // pixels hwg*2, hwg*2+1 ; d-lane 0..15
    __shared__ float ts_s[NSUB][257];

    int e0 = g_enc[b * HW + hwg * 2];
    int e1 = g_enc[b * HW + hwg * 2 + 1];
    int j0 = e0 - cls * NSUB;
    int j1 = e1 - cls * NSUB;
    float dot0 = 0.f, dot1 = 0.f, ss0 = 0.f, ss1 = 0.f;
    const float* sb = scores + (size_t)b * DDIM * HW + hwg * 2;
    int dbase = sp * DSEG;

    for (int d0 = 0; d0 < DSEG; d0 += 256) {
        int dg = dbase + d0;
#pragma unroll
        for (int k = 0; k < 4; k++) {
            int i = t + 512 * k;
            int j = i >> 6, q = i & 63;
            float4 v = *(const float4*)(ts + (size_t)(cls * NSUB + j) * DDIM + dg + q * 4);
            ts_s[j][q * 4 + 0] = v.x; ts_s[j][q * 4 + 1] = v.y;
            ts_s[j][q * 4 + 2] = v.z; ts_s[j][q * 4 + 3] = v.w;
        }
        __syncthreads();
#pragma unroll 4
        for (int i = 0; i < 16; i++) {
            int dc = dl + 16 * i;                 // 0..255 within chunk
            float2 v = __ldcs((const float2*)(sb + (size_t)(dg + dc) * HW));
            float t0 = ts_s[j0][dc];
            float t1 = ts_s[j1][dc];
            dot0 = fmaf(t0, v.x, dot0); ss0 += __expf(v.x);
            dot1 = fmaf(t1, v.y, dot1); ss1 += __expf(v.y);
        }
        __syncthreads();
    }

    __shared__ float rs[16][66], rd[16][66];
    rs[dl][hwg * 2] = ss0; rs[dl][hwg * 2 + 1] = ss1;
    rd[dl][hwg * 2] = dot0; rd[dl][hwg * 2 + 1] = dot1;
    __syncthreads();
    if (t < 64) {
        float S = 0.f, D = 0.f;
#pragma unroll
        for (int l = 0; l < 16; l++) { S += rs[l][t]; D += rd[l][t]; }
        g_pssum[sp][b * HW + t] = S;
        g_pdot [sp][b * HW + t] = D;
    }
}

// ---------------------------------------------------------------- merge (64 blocks)
__global__ void k_merge(void) {
    int bx = blockIdx.x;        // 64
    int t  = threadIdx.x;       // 128
    int r  = bx * 128 + t;
    int e = g_enc[r];
    float ss = 0.f, dd = 0.f;
#pragma unroll
    for (int sp = 0; sp < SPLIT; sp++) { ss += g_pssum[sp][r]; dd += g_pdot[sp][r]; }
    float acc = g_T1[e] - dd + g_Tsum[e] * __logf(ss);
    acc = warp_sum(acc);
    __shared__ float sh[4];
    if ((t & 31) == 0) sh[t >> 5] = acc;
    __syncthreads();
    if (t == 0) g_mpart[bx] = sh[0] + sh[1] + sh[2] + sh[3];
}

// ---------------------------------------------------------------- final
__global__ void k_final(float* __restrict__ out) {
    int t = threadIdx.x;   // 64
    float v = g_mpart[t];
    v = warp_sum(v);
    __shared__ float sh[2];
    if ((t & 31) == 0) sh[t >> 5] = v;
    __syncthreads();
    if (t == 0) out[0] = (sh[0] + sh[1]) / (float)NROWS;
}

extern "C" void kernel_launch(void* const* d_in, const int* in_sizes, int n_in,
                              void* d_out, int out_size) {
    const float* feat   = (const float*)d_in[0];
    const float* scores = (const float*)d_in[1];
    const int*   labels = (const int*)  d_in[2];
    const float* W      = (const float*)d_in[3];
    const float* bias   = (const float*)d_in[4];
    const float* cc     = (const float*)d_in[5];
    const float* ts     = (const float*)d_in[6];
    float* out = (float*)d_out;

    k_present<<<1, 128>>>(labels);
    k_setup<<<GBLK + EMB, 128>>>(cc, W, bias, ts);
    k_argmin_part<<<B_ * CSPL, 256>>>(feat, labels);
    k_argmin_fin<<<B_, 64>>>(labels);
    k_main<<<B_ * SPLIT, 512>>>(scores, ts, labels);
    k_merge<<<64, 128>>>();
    k_final<<<1, 64>>>(out);
}